// round 9
// baseline (speedup 1.0000x reference)
#include <cuda_runtime.h>
#include <cuda_fp16.h>

#define TW 2048
#define WA 49
#define NQ (TW*WA)
#define NKV (3*TW*WA)
#define CIN 512
#define D 256
#define SCALE_F 0.17677669529663687f

__device__ __half gWq_h[D*CIN];
__device__ __half gWkv_h[2*D*CIN];
__device__ __half gWp_h[D*D];
__device__ __half gQh[(size_t)NQ*D], gQl[(size_t)NQ*D];
__device__ __half gK[(size_t)NKV*D], gV[(size_t)NKV*D];
__device__ float  gO[(size_t)NQ*D];

__device__ __forceinline__ void fsplit(float v, __half& hi, __half& lo){
    hi = __float2half_rn(v);
    lo = __float2half_rn(v - __half2float(hi));
}

__device__ __forceinline__ void mma16816(float c[4], const unsigned a[4], unsigned b0, unsigned b1){
    asm volatile(
      "mma.sync.aligned.m16n8k16.row.col.f32.f16.f16.f32 "
      "{%0,%1,%2,%3},{%4,%5,%6,%7},{%8,%9},{%0,%1,%2,%3};\n"
      : "+f"(c[0]), "+f"(c[1]), "+f"(c[2]), "+f"(c[3])
      : "r"(a[0]), "r"(a[1]), "r"(a[2]), "r"(a[3]), "r"(b0), "r"(b1));
}

__device__ __forceinline__ void ldsm4(unsigned addr, unsigned r[4]){
    asm volatile("ldmatrix.sync.aligned.m8n8.x4.shared.b16 {%0,%1,%2,%3}, [%4];\n"
      : "=r"(r[0]), "=r"(r[1]), "=r"(r[2]), "=r"(r[3]) : "r"(addr));
}

__global__ void prep_weights(const float* __restrict__ Wq, const float* __restrict__ Wk,
                             const float* __restrict__ Wv, const float* __restrict__ Wp){
    int i0 = blockIdx.x*blockDim.x + threadIdx.x, st = gridDim.x*blockDim.x;
    for (int i=i0; i<D*CIN; i+=st){ int n=i/CIN, k=i%CIN; gWq_h[i] = __float2half_rn(Wq[k*D+n]); }
    for (int i=i0; i<2*D*CIN; i+=st){ int n=i/CIN, k=i%CIN;
        float v = (n<D) ? Wk[k*D+n] : Wv[k*D+n-D]; gWkv_h[i] = __float2half_rn(v); }
    for (int i=i0; i<D*D; i+=st){ int n=i/D, k=i%D; gWp_h[i] = __float2half_rn(Wp[k*D+n]); }
}

// 128x128-tile split-fp16 GEMM (2 products: Ah*B + Al*B), double-buffered, ldmatrix.
// EPI 0: Q proj, 1: K|V proj, 2: out proj.
#define SSTR 56
#define SLAB (128*SSTR)
#define GEMM_SMEM (6*SLAB*2)   // sAh[2] sAl[2] sBh[2] -> 86016 B

template<int EPI>
__global__ __launch_bounds__(256,2)
void gemm128(int KT, const float* __restrict__ A,
             const float* __restrict__ bias0, const float* __restrict__ bias1,
             float* __restrict__ outF)
{
    extern __shared__ __half smh[];
    __half* sAh = smh;
    __half* sAl = smh + 2*SLAB;
    __half* sBh = smh + 4*SLAB;

    const int tid = threadIdx.x, lane = tid&31, warp = tid>>5;
    const int wm = warp>>1, wn = warp&1;
    const int m0 = blockIdx.y*128, n0 = blockIdx.x*128;
    const __half* Bh = (EPI==0)?gWq_h:(EPI==1)?gWkv_h:gWp_h;
    const float*  Ap = (EPI==2)?gO:A;

    // staging indices
    const int arA[4] = { (tid+0)>>3, (tid+256)>>3, (tid+512)>>3, (tid+768)>>3 };
    const int acA    = (tid&7)<<2;
    const int brB[2] = { (tid+0)>>2, (tid+256)>>2 };
    const int bcB    = (tid&3)<<3;

    // ldmatrix per-lane bases (halves offsets within a buffer)
    const unsigned smbase = (unsigned)__cvta_generic_to_shared(smh);
    const int aoff = (wm*32 + (lane&15))*SSTR + ((lane&16)?8:0);
    const int boff = (wn*64 + (lane&7) + ((lane&16)?8:0))*SSTR + ((lane&8)?8:0);

    float acc[2][8][4] = {};
    float4 pa[4]; uint4 pb[2];

    const int NS = KT >> 5;

    // prologue: slab 0
    #pragma unroll
    for (int i=0;i<4;i++) pa[i] = *(const float4*)(Ap + (size_t)(m0+arA[i])*KT + acA);
    #pragma unroll
    for (int i=0;i<2;i++) pb[i] = *(const uint4*)(Bh + (size_t)(n0+brB[i])*KT + bcB);
    #pragma unroll
    for (int i=0;i<4;i++){
        int o = arA[i]*SSTR + acA;
        fsplit(pa[i].x, sAh[o],   sAl[o]);
        fsplit(pa[i].y, sAh[o+1], sAl[o+1]);
        fsplit(pa[i].z, sAh[o+2], sAl[o+2]);
        fsplit(pa[i].w, sAh[o+3], sAl[o+3]);
    }
    #pragma unroll
    for (int i=0;i<2;i++) *(uint4*)&sBh[brB[i]*SSTR + bcB] = pb[i];
    __syncthreads();

    for (int s=0; s<NS; s++){
        const int buf = s&1;
        const bool more = (s+1 < NS);
        if (more){
            const int kk = (s+1)<<5;
            #pragma unroll
            for (int i=0;i<4;i++) pa[i] = *(const float4*)(Ap + (size_t)(m0+arA[i])*KT + kk + acA);
            #pragma unroll
            for (int i=0;i<2;i++) pb[i] = *(const uint4*)(Bh + (size_t)(n0+brB[i])*KT + kk + bcB);
        }
        const unsigned aH = smbase + (unsigned)(buf*SLAB + aoff)*2u;
        const unsigned aL = smbase + (unsigned)(2*SLAB + buf*SLAB + aoff)*2u;
        const unsigned bB = smbase + (unsigned)(4*SLAB + buf*SLAB + boff)*2u;
        #pragma unroll
        for (int ks=0; ks<2; ks++){
            unsigned ah[2][4], al[2][4];
            #pragma unroll
            for (int mt=0;mt<2;mt++){
                ldsm4(aH + (unsigned)(mt*16*SSTR + ks*16)*2u, ah[mt]);
                ldsm4(aL + (unsigned)(mt*16*SSTR + ks*16)*2u, al[mt]);
            }
            #pragma unroll
            for (int nt2=0; nt2<4; nt2++){
                unsigned bb[4];
                ldsm4(bB + (unsigned)(nt2*16*SSTR + ks*16)*2u, bb);
                #pragma unroll
                for (int mt=0;mt<2;mt++){
                    mma16816(acc[mt][2*nt2],   ah[mt], bb[0], bb[1]);
                    mma16816(acc[mt][2*nt2],   al[mt], bb[0], bb[1]);
                    mma16816(acc[mt][2*nt2+1], ah[mt], bb[2], bb[3]);
                    mma16816(acc[mt][2*nt2+1], al[mt], bb[2], bb[3]);
                }
            }
        }
        if (more){
            const int nb = buf^1;
            #pragma unroll
            for (int i=0;i<4;i++){
                int o = nb*SLAB + arA[i]*SSTR + acA;
                fsplit(pa[i].x, sAh[o],   sAl[o]);
                fsplit(pa[i].y, sAh[o+1], sAl[o+1]);
                fsplit(pa[i].z, sAh[o+2], sAl[o+2]);
                fsplit(pa[i].w, sAh[o+3], sAl[o+3]);
            }
            #pragma unroll
            for (int i=0;i<2;i++) *(uint4*)&sBh[nb*SLAB + brB[i]*SSTR + bcB] = pb[i];
        }
        __syncthreads();
    }

    #pragma unroll
    for (int mt=0;mt<2;mt++){
        #pragma unroll
        for (int nt=0;nt<8;nt++){
            int r = m0 + wm*32 + mt*16 + (lane>>2);
            int c = n0 + wn*64 + nt*8 + (lane&3)*2;
            float v00=acc[mt][nt][0], v01=acc[mt][nt][1];
            float v10=acc[mt][nt][2], v11=acc[mt][nt][3];
            if (EPI == 0){
                float b0=bias0[c], b1=bias0[c+1];
                __half h0,l0,h1,l1;
                fsplit(v00+b0,h0,l0); fsplit(v01+b1,h1,l1);
                *(__half2*)&gQh[(size_t)r*D+c] = __halves2half2(h0,h1);
                *(__half2*)&gQl[(size_t)r*D+c] = __halves2half2(l0,l1);
                fsplit(v10+b0,h0,l0); fsplit(v11+b1,h1,l1);
                *(__half2*)&gQh[(size_t)(r+8)*D+c] = __halves2half2(h0,h1);
                *(__half2*)&gQl[(size_t)(r+8)*D+c] = __halves2half2(l0,l1);
            } else if (EPI == 1){
                bool isV = (c >= D);
                __half* dst = isV ? gV : gK;
                const float* bb = isV ? bias1 : bias0;
                int cc = c & (D-1);
                float b0=bb[cc], b1=bb[cc+1];
                *(__half2*)&dst[(size_t)r*D+cc]     = __floats2half2_rn(v00+b0, v01+b1);
                *(__half2*)&dst[(size_t)(r+8)*D+cc] = __floats2half2_rn(v10+b0, v11+b1);
            } else {
                float b0=bias0[c], b1=bias0[c+1];
                outF[(size_t)r*D+c]       = v00+b0;
                outF[(size_t)r*D+c+1]     = v01+b1;
                outF[(size_t)(r+8)*D+c]   = v10+b0;
                outF[(size_t)(r+8)*D+c+1] = v11+b1;
            }
        }
    }
}

// One CTA per window. smem: Qh[64x264] Ql[64x264] | K[160x264]->VT[256x168] | S[64x160] f32 | mask
#define SMEM_BYTES 204800
__global__ __launch_bounds__(256)
void attn_kernel(const float* __restrict__ mask)
{
    extern __shared__ char sm[];
    __half* sQh = (__half*)sm;               // 33792 B
    __half* sQl = (__half*)(sm + 33792);     // 33792 B
    __half* sKV = (__half*)(sm + 67584);     // 86016 B (K 160x264, then VT 256x168)
    float*  sS  = (float*)(sm + 153600);     // 40960 B (64x160)
    float*  sM  = (float*)(sm + 194560);     // 9604 B
    __half* sPh = sQh;
    __half* sPl = sQl;

    const int tid = threadIdx.x, lane = tid&31, warp = tid>>5;
    const int t = blockIdx.x;
    const size_t qb = (size_t)t*WA*D, kvb = (size_t)t*3*WA*D;

    for (int i=tid; i<49*32; i+=256){ int r=i>>5, g=(i&31)<<3;
        *(uint4*)&sQh[r*264+g] = *(const uint4*)(gQh + qb + (size_t)r*D + g);
        *(uint4*)&sQl[r*264+g] = *(const uint4*)(gQl + qb + (size_t)r*D + g); }
    for (int i=tid; i<147*32; i+=256){ int r=i>>5, g=(i&31)<<3;
        *(uint4*)&sKV[r*264+g] = *(const uint4*)(gK + kvb + (size_t)r*D + g); }
    for (int i=tid; i<WA*WA; i+=256) sM[i] = mask[(size_t)(t&63)*WA*WA + i];
    __syncthreads();

    // S = Q @ K^T  (64x160 tile; valid 49x147)
    {
        const int wmS = warp>>1, wnS = warp&1;
        float acc[10][4] = {};
        for (int ks=0; ks<16; ks++){
            int ar = wmS*16 + (lane>>2), ac = ks*16 + (lane&3)*2;
            unsigned ah[4], al[4];
            ah[0]=*(unsigned*)&sQh[ar*264+ac];   ah[1]=*(unsigned*)&sQh[(ar+8)*264+ac];
            ah[2]=*(unsigned*)&sQh[ar*264+ac+8]; ah[3]=*(unsigned*)&sQh[(ar+8)*264+ac+8];
            al[0]=*(unsigned*)&sQl[ar*264+ac];   al[1]=*(unsigned*)&sQl[(ar+8)*264+ac];
            al[2]=*(unsigned*)&sQl[ar*264+ac+8]; al[3]=*(unsigned*)&sQl[(ar+8)*264+ac+8];
            #pragma unroll
            for (int j=0;j<10;j++){
                int br = (wnS*10+j)*8 + (lane>>2);
                unsigned b0=*(unsigned*)&sKV[br*264+ac], b1=*(unsigned*)&sKV[br*264+ac+8];
                mma16816(acc[j], ah, b0, b1);
                mma16816(acc[j], al, b0, b1);
            }
        }
        #pragma unroll
        for (int j=0;j<10;j++){
            int r = wmS*16 + (lane>>2), c = (wnS*10+j)*8 + (lane&3)*2;
            sS[r*160+c]=acc[j][0]; sS[r*160+c+1]=acc[j][1];
            sS[(r+8)*160+c]=acc[j][2]; sS[(r+8)*160+c+1]=acc[j][3];
        }
    }
    __syncthreads();

    // V transposed into sKV as VT[dim][tok] stride 168; pad toks 147..159 = 0
    for (int i=tid; i<147*32; i+=256){ int tok=i>>5, g=(i&31)<<3;
        uint4 v = *(const uint4*)(gV + kvb + (size_t)tok*D + g);
        const __half* h = (const __half*)&v;
        #pragma unroll
        for (int j=0;j<8;j++) sKV[(g+j)*168 + tok] = h[j]; }
    for (int i=tid; i<256*13; i+=256){ int d=i/13, tok=147+i%13; sKV[d*168+tok] = __float2half(0.f); }

    // softmax rows (fp32) -> split P
    for (int r=warp; r<49; r+=8){
        float vals[5]; float mx = -1e30f;
        #pragma unroll
        for (int i=0;i<5;i++){ int c = lane + 32*i; float v = -1e30f;
            if (c < 147){ int cm = (c>=98)?c-98:(c>=49)?c-49:c;
                v = sS[r*160+c]*SCALE_F + sM[r*49+cm]; }
            vals[i]=v; mx=fmaxf(mx,v); }
        #pragma unroll
        for (int o=16;o;o>>=1) mx = fmaxf(mx, __shfl_xor_sync(0xffffffffu, mx, o));
        float s = 0.f;
        #pragma unroll
        for (int i=0;i<5;i++){ int c = lane + 32*i;
            float e = (c<147) ? __expf(vals[i]-mx) : 0.f; vals[i]=e; s+=e; }
        #pragma unroll
        for (int o=16;o;o>>=1) s += __shfl_xor_sync(0xffffffffu, s, o);
        float inv = 1.f/s;
        #pragma unroll
        for (int i=0;i<5;i++){ int c = lane + 32*i; float p = vals[i]*inv;
            __half h,l; fsplit(p,h,l); sPh[r*168+c]=h; sPl[r*168+c]=l; }
    }
    __syncthreads();

    // O^T = VT @ P^T : M=256 (dims), N=64 (queries), K=160. Direct global store (dim-major).
    {
        float acc[2][8][4] = {};
        for (int ks=0; ks<10; ks++){
            int ac = ks*16 + (lane&3)*2;
            unsigned av[2][4];
            #pragma unroll
            for (int mt=0;mt<2;mt++){
                int ar = warp*32 + mt*16 + (lane>>2);
                av[mt][0]=*(unsigned*)&sKV[ar*168+ac];   av[mt][1]=*(unsigned*)&sKV[(ar+8)*168+ac];
                av[mt][2]=*(unsigned*)&sKV[ar*168+ac+8]; av[mt][3]=*(unsigned*)&sKV[(ar+8)*168+ac+8];
            }
            #pragma unroll
            for (int nt=0;nt<8;nt++){
                int br = nt*8 + (lane>>2);
                unsigned p0=*(unsigned*)&sPh[br*168+ac], p1=*(unsigned*)&sPh[br*168+ac+8];
                unsigned l0=*(unsigned*)&sPl[br*168+ac], l1=*(unsigned*)&sPl[br*168+ac+8];
                #pragma unroll
                for (int mt=0;mt<2;mt++){
                    mma16816(acc[mt][nt], av[mt], p0, p1);
                    mma16816(acc[mt][nt], av[mt], l0, l1);
                }
            }
        }
        float* Ow = gO + (size_t)t*WA*D;
        #pragma unroll
        for (int mt=0;mt<2;mt++){
            #pragma unroll
            for (int nt=0;nt<8;nt++){
                int d0 = warp*32 + mt*16 + (lane>>2);
                int q  = nt*8 + (lane&3)*2;
                if (q < 49){ Ow[d0*49+q]     = acc[mt][nt][0]; Ow[(d0+8)*49+q]   = acc[mt][nt][2]; }
                if (q+1 < 49){ Ow[d0*49+q+1] = acc[mt][nt][1]; Ow[(d0+8)*49+q+1] = acc[mt][nt][3]; }
            }
        }
    }
}

extern "C" void kernel_launch(void* const* d_in, const int* in_sizes, int n_in,
                              void* d_out, int out_size)
{
    const float* x    = (const float*)d_in[0];
    const float* mask = (const float*)d_in[1];
    const float* Wq = (const float*)d_in[2]; const float* bq = (const float*)d_in[3];
    const float* Wk = (const float*)d_in[4]; const float* bk = (const float*)d_in[5];
    const float* Wv = (const float*)d_in[6]; const float* bv = (const float*)d_in[7];
    const float* Wp = (const float*)d_in[8]; const float* bp = (const float*)d_in[9];
    float* out = (float*)d_out;

    cudaFuncSetAttribute(attn_kernel, cudaFuncAttributeMaxDynamicSharedMemorySize, SMEM_BYTES);
    cudaFuncSetAttribute(gemm128<0>, cudaFuncAttributeMaxDynamicSharedMemorySize, GEMM_SMEM);
    cudaFuncSetAttribute(gemm128<1>, cudaFuncAttributeMaxDynamicSharedMemorySize, GEMM_SMEM);
    cudaFuncSetAttribute(gemm128<2>, cudaFuncAttributeMaxDynamicSharedMemorySize, GEMM_SMEM);

    prep_weights<<<256,256>>>(Wq, Wk, Wv, Wp);
    gemm128<0><<<dim3(2,784), 256, GEMM_SMEM>>>(CIN, x + (size_t)3*TW*WA*CIN, bq, nullptr, nullptr);
    gemm128<1><<<dim3(4,2352), 256, GEMM_SMEM>>>(CIN, x, bk, bv, nullptr);
    attn_kernel<<<TW, 256, SMEM_BYTES>>>(mask);
    gemm128<2><<<dim3(2,784), 256, GEMM_SMEM>>>(D, nullptr, bp, nullptr, out);
}

// round 10
// speedup vs baseline: 1.1023x; 1.1023x over previous
#include <cuda_runtime.h>
#include <cuda_fp16.h>

#define TW 2048
#define WA 49
#define NQ (TW*WA)
#define NKV (3*TW*WA)
#define CIN 512
#define D 256
#define SCALE_F 0.17677669529663687f

__device__ __half gWq_h[D*CIN];
__device__ __half gWkv_h[2*D*CIN];
__device__ __half gWp_h[D*D];
__device__ __half gQh[(size_t)NQ*D], gQl[(size_t)NQ*D];
__device__ __half gK[(size_t)NKV*D], gV[(size_t)NKV*D];
__device__ float  gO[(size_t)NQ*D];

__device__ __forceinline__ void fsplit(float v, __half& hi, __half& lo){
    hi = __float2half_rn(v);
    lo = __float2half_rn(v - __half2float(hi));
}

__device__ __forceinline__ void mma16816(float c[4], const unsigned a[4], unsigned b0, unsigned b1){
    asm volatile(
      "mma.sync.aligned.m16n8k16.row.col.f32.f16.f16.f32 "
      "{%0,%1,%2,%3},{%4,%5,%6,%7},{%8,%9},{%0,%1,%2,%3};\n"
      : "+f"(c[0]), "+f"(c[1]), "+f"(c[2]), "+f"(c[3])
      : "r"(a[0]), "r"(a[1]), "r"(a[2]), "r"(a[3]), "r"(b0), "r"(b1));
}

__device__ __forceinline__ void ldsm4(unsigned addr, unsigned r[4]){
    asm volatile("ldmatrix.sync.aligned.m8n8.x4.shared.b16 {%0,%1,%2,%3}, [%4];\n"
      : "=r"(r[0]), "=r"(r[1]), "=r"(r[2]), "=r"(r[3]) : "r"(addr));
}

__device__ __forceinline__ void ldsm4t(unsigned addr, unsigned r[4]){
    asm volatile("ldmatrix.sync.aligned.m8n8.x4.trans.shared.b16 {%0,%1,%2,%3}, [%4];\n"
      : "=r"(r[0]), "=r"(r[1]), "=r"(r[2]), "=r"(r[3]) : "r"(addr));
}

__global__ void prep_weights(const float* __restrict__ Wq, const float* __restrict__ Wk,
                             const float* __restrict__ Wv, const float* __restrict__ Wp){
    int i0 = blockIdx.x*blockDim.x + threadIdx.x, st = gridDim.x*blockDim.x;
    for (int i=i0; i<D*CIN; i+=st){ int n=i/CIN, k=i%CIN; gWq_h[i] = __float2half_rn(Wq[k*D+n]); }
    for (int i=i0; i<2*D*CIN; i+=st){ int n=i/CIN, k=i%CIN;
        float v = (n<D) ? Wk[k*D+n] : Wv[k*D+n-D]; gWkv_h[i] = __float2half_rn(v); }
    for (int i=i0; i<D*D; i+=st){ int n=i/D, k=i%D; gWp_h[i] = __float2half_rn(Wp[k*D+n]); }
}

// 128x128-tile split-fp16 GEMM (2 products: Ah*B + Al*B), double-buffered, ldmatrix.
#define SSTR 56
#define SLAB (128*SSTR)
#define GEMM_SMEM (6*SLAB*2)

template<int EPI>
__global__ __launch_bounds__(256,2)
void gemm128(int KT, const float* __restrict__ A,
             const float* __restrict__ bias0, const float* __restrict__ bias1,
             float* __restrict__ outF)
{
    extern __shared__ __half smh[];
    __half* sAh = smh;
    __half* sAl = smh + 2*SLAB;
    __half* sBh = smh + 4*SLAB;

    const int tid = threadIdx.x, lane = tid&31, warp = tid>>5;
    const int wm = warp>>1, wn = warp&1;
    const int m0 = blockIdx.y*128, n0 = blockIdx.x*128;
    const __half* Bh = (EPI==0)?gWq_h:(EPI==1)?gWkv_h:gWp_h;
    const float*  Ap = (EPI==2)?gO:A;

    const int arA[4] = { (tid+0)>>3, (tid+256)>>3, (tid+512)>>3, (tid+768)>>3 };
    const int acA    = (tid&7)<<2;
    const int brB[2] = { (tid+0)>>2, (tid+256)>>2 };
    const int bcB    = (tid&3)<<3;

    const unsigned smbase = (unsigned)__cvta_generic_to_shared(smh);
    const int aoff = (wm*32 + (lane&15))*SSTR + ((lane&16)?8:0);
    const int boff = (wn*64 + (lane&7) + ((lane&16)?8:0))*SSTR + ((lane&8)?8:0);

    float acc[2][8][4] = {};
    float4 pa[4]; uint4 pb[2];

    const int NS = KT >> 5;

    #pragma unroll
    for (int i=0;i<4;i++) pa[i] = *(const float4*)(Ap + (size_t)(m0+arA[i])*KT + acA);
    #pragma unroll
    for (int i=0;i<2;i++) pb[i] = *(const uint4*)(Bh + (size_t)(n0+brB[i])*KT + bcB);
    #pragma unroll
    for (int i=0;i<4;i++){
        int o = arA[i]*SSTR + acA;
        fsplit(pa[i].x, sAh[o],   sAl[o]);
        fsplit(pa[i].y, sAh[o+1], sAl[o+1]);
        fsplit(pa[i].z, sAh[o+2], sAl[o+2]);
        fsplit(pa[i].w, sAh[o+3], sAl[o+3]);
    }
    #pragma unroll
    for (int i=0;i<2;i++) *(uint4*)&sBh[brB[i]*SSTR + bcB] = pb[i];
    __syncthreads();

    for (int s=0; s<NS; s++){
        const int buf = s&1;
        const bool more = (s+1 < NS);
        if (more){
            const int kk = (s+1)<<5;
            #pragma unroll
            for (int i=0;i<4;i++) pa[i] = *(const float4*)(Ap + (size_t)(m0+arA[i])*KT + kk + acA);
            #pragma unroll
            for (int i=0;i<2;i++) pb[i] = *(const uint4*)(Bh + (size_t)(n0+brB[i])*KT + kk + bcB);
        }
        const unsigned aH = smbase + (unsigned)(buf*SLAB + aoff)*2u;
        const unsigned aL = smbase + (unsigned)(2*SLAB + buf*SLAB + aoff)*2u;
        const unsigned bB = smbase + (unsigned)(4*SLAB + buf*SLAB + boff)*2u;
        #pragma unroll
        for (int ks=0; ks<2; ks++){
            unsigned ah[2][4], al[2][4];
            #pragma unroll
            for (int mt=0;mt<2;mt++){
                ldsm4(aH + (unsigned)(mt*16*SSTR + ks*16)*2u, ah[mt]);
                ldsm4(aL + (unsigned)(mt*16*SSTR + ks*16)*2u, al[mt]);
            }
            #pragma unroll
            for (int nt2=0; nt2<4; nt2++){
                unsigned bb[4];
                ldsm4(bB + (unsigned)(nt2*16*SSTR + ks*16)*2u, bb);
                #pragma unroll
                for (int mt=0;mt<2;mt++){
                    mma16816(acc[mt][2*nt2],   ah[mt], bb[0], bb[1]);
                    mma16816(acc[mt][2*nt2],   al[mt], bb[0], bb[1]);
                    mma16816(acc[mt][2*nt2+1], ah[mt], bb[2], bb[3]);
                    mma16816(acc[mt][2*nt2+1], al[mt], bb[2], bb[3]);
                }
            }
        }
        if (more){
            const int nb = buf^1;
            #pragma unroll
            for (int i=0;i<4;i++){
                int o = nb*SLAB + arA[i]*SSTR + acA;
                fsplit(pa[i].x, sAh[o],   sAl[o]);
                fsplit(pa[i].y, sAh[o+1], sAl[o+1]);
                fsplit(pa[i].z, sAh[o+2], sAl[o+2]);
                fsplit(pa[i].w, sAh[o+3], sAl[o+3]);
            }
            #pragma unroll
            for (int i=0;i<2;i++) *(uint4*)&sBh[nb*SLAB + brB[i]*SSTR + bcB] = pb[i];
        }
        __syncthreads();
    }

    #pragma unroll
    for (int mt=0;mt<2;mt++){
        #pragma unroll
        for (int nt=0;nt<8;nt++){
            int r = m0 + wm*32 + mt*16 + (lane>>2);
            int c = n0 + wn*64 + nt*8 + (lane&3)*2;
            float v00=acc[mt][nt][0], v01=acc[mt][nt][1];
            float v10=acc[mt][nt][2], v11=acc[mt][nt][3];
            if (EPI == 0){
                float b0=bias0[c], b1=bias0[c+1];
                __half h0,l0,h1,l1;
                fsplit(v00+b0,h0,l0); fsplit(v01+b1,h1,l1);
                *(__half2*)&gQh[(size_t)r*D+c] = __halves2half2(h0,h1);
                *(__half2*)&gQl[(size_t)r*D+c] = __halves2half2(l0,l1);
                fsplit(v10+b0,h0,l0); fsplit(v11+b1,h1,l1);
                *(__half2*)&gQh[(size_t)(r+8)*D+c] = __halves2half2(h0,h1);
                *(__half2*)&gQl[(size_t)(r+8)*D+c] = __halves2half2(l0,l1);
            } else if (EPI == 1){
                bool isV = (c >= D);
                __half* dst = isV ? gV : gK;
                const float* bb = isV ? bias1 : bias0;
                int cc = c & (D-1);
                float b0=bb[cc], b1=bb[cc+1];
                *(__half2*)&dst[(size_t)r*D+cc]     = __floats2half2_rn(v00+b0, v01+b1);
                *(__half2*)&dst[(size_t)(r+8)*D+cc] = __floats2half2_rn(v10+b0, v11+b1);
            } else {
                float b0=bias0[c], b1=bias0[c+1];
                outF[(size_t)r*D+c]       = v00+b0;
                outF[(size_t)r*D+c+1]     = v01+b1;
                outF[(size_t)(r+8)*D+c]   = v10+b0;
                outF[(size_t)(r+8)*D+c+1] = v11+b1;
            }
        }
    }
}

// One CTA per window. smem: Qh[64x264] | Ql[64x264] | KV[160x264] | S[64x160] f32 | mask[49x49]
// P (hi/lo, 64x168) reuses the Qh/Ql regions after softmax.
#define SMEM_BYTES 202752
__global__ __launch_bounds__(256)
void attn_kernel(const float* __restrict__ mask)
{
    extern __shared__ char sm[];
    __half* sQh = (__half*)sm;                // 33792 B
    __half* sQl = (__half*)(sm + 33792);      // 33792 B
    __half* sKV = (__half*)(sm + 67584);      // 84480 B (K rows 0..146; V reuses; rows 147..159 zero)
    float*  sS  = (float*)(sm + 152064);      // 40960 B (64x160)
    float*  sM  = (float*)(sm + 193024);      // 9604 B
    __half* sPh = sQh;
    __half* sPl = sQl;

    const int tid = threadIdx.x, lane = tid&31, warp = tid>>5;
    const int t = blockIdx.x;
    const size_t qb = (size_t)t*WA*D, kvb = (size_t)t*3*WA*D;
    const unsigned smb = (unsigned)__cvta_generic_to_shared(sm);

    for (int i=tid; i<49*32; i+=256){ int r=i>>5, g=(i&31)<<3;
        *(uint4*)&sQh[r*264+g] = *(const uint4*)(gQh + qb + (size_t)r*D + g);
        *(uint4*)&sQl[r*264+g] = *(const uint4*)(gQl + qb + (size_t)r*D + g); }
    for (int i=tid; i<147*32; i+=256){ int r=i>>5, g=(i&31)<<3;
        *(uint4*)&sKV[r*264+g] = *(const uint4*)(gK + kvb + (size_t)r*D + g); }
    // zero pad rows 147..159 (incl. stride padding) once; V reload keeps them zero
    for (int i=tid; i<13*33; i+=256){ int r=147 + i/33, c=(i%33)*8;
        *(uint4*)&sKV[r*264+c] = make_uint4(0,0,0,0); }
    for (int i=tid; i<WA*WA; i+=256) sM[i] = mask[(size_t)(t&63)*WA*WA + i];
    __syncthreads();

    // ---- S = Q @ K^T  (64x160 tile; valid 49x147), ldmatrix + split-Q mma ----
    {
        const int wmS = warp>>1, wnS = warp&1;
        const unsigned aQh = smb + (unsigned)((wmS*16 + (lane&15))*264 + ((lane&16)?8:0))*2u;
        const unsigned aQl = aQh + 33792u;
        const unsigned bK  = smb + 67584u
            + (unsigned)((wnS*80 + (lane&7) + ((lane&16)?8:0))*264 + ((lane&8)?8:0))*2u;
        float acc[10][4] = {};
        #pragma unroll
        for (int ks=0; ks<16; ks++){
            unsigned ah[4], al[4];
            ldsm4(aQh + ks*32u, ah);
            ldsm4(aQl + ks*32u, al);
            #pragma unroll
            for (int nt2=0; nt2<5; nt2++){
                unsigned bb[4];
                ldsm4(bK + (unsigned)(nt2*16*264)*2u + ks*32u, bb);
                mma16816(acc[2*nt2],   ah, bb[0], bb[1]);
                mma16816(acc[2*nt2],   al, bb[0], bb[1]);
                mma16816(acc[2*nt2+1], ah, bb[2], bb[3]);
                mma16816(acc[2*nt2+1], al, bb[2], bb[3]);
            }
        }
        #pragma unroll
        for (int j=0;j<10;j++){
            int r = wmS*16 + (lane>>2), c = (wnS*10+j)*8 + (lane&3)*2;
            sS[r*160+c]=acc[j][0]; sS[r*160+c+1]=acc[j][1];
            sS[(r+8)*160+c]=acc[j][2]; sS[(r+8)*160+c+1]=acc[j][3];
        }
    }
    __syncthreads();

    // ---- load V row-major into sKV (pad rows stay zero) ----
    for (int i=tid; i<147*32; i+=256){ int r=i>>5, g=(i&31)<<3;
        *(uint4*)&sKV[r*264+g] = *(const uint4*)(gV + kvb + (size_t)r*D + g); }

    // ---- softmax rows (fp32) -> split P (stride 168; cols 147..159 = 0) ----
    for (int r=warp; r<49; r+=8){
        float vals[5]; float mx = -1e30f;
        #pragma unroll
        for (int i=0;i<5;i++){ int c = lane + 32*i; float v = -1e30f;
            if (c < 147){ int cm = (c>=98)?c-98:(c>=49)?c-49:c;
                v = sS[r*160+c]*SCALE_F + sM[r*49+cm]; }
            vals[i]=v; mx=fmaxf(mx,v); }
        #pragma unroll
        for (int o=16;o;o>>=1) mx = fmaxf(mx, __shfl_xor_sync(0xffffffffu, mx, o));
        float s = 0.f;
        #pragma unroll
        for (int i=0;i<5;i++){ int c = lane + 32*i;
            float e = (c<147) ? __expf(vals[i]-mx) : 0.f; vals[i]=e; s+=e; }
        #pragma unroll
        for (int o=16;o;o>>=1) s += __shfl_xor_sync(0xffffffffu, s, o);
        float inv = 1.f/s;
        #pragma unroll
        for (int i=0;i<5;i++){ int c = lane + 32*i; float p = vals[i]*inv;
            __half h,l; fsplit(p,h,l); sPh[r*168+c]=h; sPl[r*168+c]=l; }
    }
    // zero P rows 49..63 so PV accs stay finite everywhere
    for (int i=tid; i<15*21; i+=256){ int r=49 + i/21, c=(i%21)*8;
        *(uint4*)&sPh[r*168+c] = make_uint4(0,0,0,0);
        *(uint4*)&sPl[r*168+c] = make_uint4(0,0,0,0); }
    __syncthreads();

    // ---- O = P @ V : M=64 (q), N=256 (d), K=160 (toks). ldmatrix + trans-B. ----
    {
        const int wmP = warp&1, wnP = warp>>1;
        const unsigned aPh = smb + (unsigned)((wmP*32 + (lane&15))*168 + ((lane&16)?8:0))*2u;
        const unsigned aPl = aPh + 33792u;
        const unsigned bV  = smb + 67584u
            + (unsigned)((lane&15)*264 + wnP*64 + ((lane&16)?8:0))*2u;
        float acc[2][8][4] = {};
        #pragma unroll
        for (int ks=0; ks<10; ks++){
            unsigned ph[2][4], pl[2][4];
            #pragma unroll
            for (int mt=0;mt<2;mt++){
                ldsm4(aPh + (unsigned)(mt*16*168 + ks*16)*2u, ph[mt]);
                ldsm4(aPl + (unsigned)(mt*16*168 + ks*16)*2u, pl[mt]);
            }
            #pragma unroll
            for (int nt2=0; nt2<4; nt2++){
                unsigned vb[4];
                ldsm4t(bV + (unsigned)(ks*16*264 + nt2*16)*2u, vb);
                #pragma unroll
                for (int mt=0;mt<2;mt++){
                    mma16816(acc[mt][2*nt2],   ph[mt], vb[0], vb[1]);
                    mma16816(acc[mt][2*nt2],   pl[mt], vb[0], vb[1]);
                    mma16816(acc[mt][2*nt2+1], ph[mt], vb[2], vb[3]);
                    mma16816(acc[mt][2*nt2+1], pl[mt], vb[2], vb[3]);
                }
            }
        }
        float* Ow = gO + (size_t)t*WA*D;
        #pragma unroll
        for (int mt=0;mt<2;mt++){
            #pragma unroll
            for (int nt=0;nt<8;nt++){
                int q  = wmP*32 + mt*16 + (lane>>2);
                int d0 = wnP*64 + nt*8 + (lane&3)*2;
                if (q < 49){
                    Ow[d0*49+q]     = acc[mt][nt][0];
                    Ow[(d0+1)*49+q] = acc[mt][nt][1];
                }
                if (q+8 < 49){
                    Ow[d0*49+q+8]     = acc[mt][nt][2];
                    Ow[(d0+1)*49+q+8] = acc[mt][nt][3];
                }
            }
        }
    }
}

extern "C" void kernel_launch(void* const* d_in, const int* in_sizes, int n_in,
                              void* d_out, int out_size)
{
    const float* x    = (const float*)d_in[0];
    const float* mask = (const float*)d_in[1];
    const float* Wq = (const float*)d_in[2]; const float* bq = (const float*)d_in[3];
    const float* Wk = (const float*)d_in[4]; const float* bk = (const float*)d_in[5];
    const float* Wv = (const float*)d_in[6]; const float* bv = (const float*)d_in[7];
    const float* Wp = (const float*)d_in[8]; const float* bp = (const float*)d_in[9];
    float* out = (float*)d_out;

    cudaFuncSetAttribute(attn_kernel, cudaFuncAttributeMaxDynamicSharedMemorySize, SMEM_BYTES);
    cudaFuncSetAttribute(gemm128<0>, cudaFuncAttributeMaxDynamicSharedMemorySize, GEMM_SMEM);
    cudaFuncSetAttribute(gemm128<1>, cudaFuncAttributeMaxDynamicSharedMemorySize, GEMM_SMEM);
    cudaFuncSetAttribute(gemm128<2>, cudaFuncAttributeMaxDynamicSharedMemorySize, GEMM_SMEM);

    prep_weights<<<256,256>>>(Wq, Wk, Wv, Wp);
    gemm128<0><<<dim3(2,784), 256, GEMM_SMEM>>>(CIN, x + (size_t)3*TW*WA*CIN, bq, nullptr, nullptr);
    gemm128<1><<<dim3(4,2352), 256, GEMM_SMEM>>>(CIN, x, bk, bv, nullptr);
    attn_kernel<<<TW, 256, SMEM_BYTES>>>(mask);
    gemm128<2><<<dim3(2,784), 256, GEMM_SMEM>>>(D, nullptr, bp, nullptr, out);
}

// round 11
// speedup vs baseline: 1.3254x; 1.2024x over previous
#include <cuda_runtime.h>
#include <cuda_fp16.h>

#define TW 2048
#define WA 49
#define NQ (TW*WA)
#define NKV (3*TW*WA)
#define CIN 512
#define D 256
#define SCALE_F 0.17677669529663687f

__device__ __half gWq_h[D*CIN];
__device__ __half gWkv_h[2*D*CIN];
__device__ __half gWp_h[D*D];
__device__ __half gQh[(size_t)NQ*D];
__device__ __half gK[(size_t)NKV*D], gV[(size_t)NKV*D];
__device__ float  gO[(size_t)NQ*D];

__device__ __forceinline__ void fsplit(float v, __half& hi, __half& lo){
    hi = __float2half_rn(v);
    lo = __float2half_rn(v - __half2float(hi));
}

__device__ __forceinline__ void mma16816(float c[4], const unsigned a[4], unsigned b0, unsigned b1){
    asm volatile(
      "mma.sync.aligned.m16n8k16.row.col.f32.f16.f16.f32 "
      "{%0,%1,%2,%3},{%4,%5,%6,%7},{%8,%9},{%0,%1,%2,%3};\n"
      : "+f"(c[0]), "+f"(c[1]), "+f"(c[2]), "+f"(c[3])
      : "r"(a[0]), "r"(a[1]), "r"(a[2]), "r"(a[3]), "r"(b0), "r"(b1));
}

__device__ __forceinline__ void ldsm4(unsigned addr, unsigned r[4]){
    asm volatile("ldmatrix.sync.aligned.m8n8.x4.shared.b16 {%0,%1,%2,%3}, [%4];\n"
      : "=r"(r[0]), "=r"(r[1]), "=r"(r[2]), "=r"(r[3]) : "r"(addr));
}

__device__ __forceinline__ void ldsm4t(unsigned addr, unsigned r[4]){
    asm volatile("ldmatrix.sync.aligned.m8n8.x4.trans.shared.b16 {%0,%1,%2,%3}, [%4];\n"
      : "=r"(r[0]), "=r"(r[1]), "=r"(r[2]), "=r"(r[3]) : "r"(addr));
}

__device__ __forceinline__ void cpa16(unsigned dst, const void* src){
    asm volatile("cp.async.cg.shared.global [%0], [%1], 16;\n" :: "r"(dst), "l"(src) : "memory");
}
__device__ __forceinline__ void cpa4(unsigned dst, const void* src){
    asm volatile("cp.async.ca.shared.global [%0], [%1], 4;\n" :: "r"(dst), "l"(src) : "memory");
}
#define CP_COMMIT()  asm volatile("cp.async.commit_group;\n" ::: "memory")
#define CP_WAIT0()   asm volatile("cp.async.wait_group 0;\n" ::: "memory")
#define CP_WAIT1()   asm volatile("cp.async.wait_group 1;\n" ::: "memory")

__global__ void prep_weights(const float* __restrict__ Wq, const float* __restrict__ Wk,
                             const float* __restrict__ Wv, const float* __restrict__ Wp){
    int i0 = blockIdx.x*blockDim.x + threadIdx.x, st = gridDim.x*blockDim.x;
    for (int i=i0; i<D*CIN; i+=st){ int n=i/CIN, k=i%CIN; gWq_h[i] = __float2half_rn(Wq[k*D+n]); }
    for (int i=i0; i<2*D*CIN; i+=st){ int n=i/CIN, k=i%CIN;
        float v = (n<D) ? Wk[k*D+n] : Wv[k*D+n-D]; gWkv_h[i] = __float2half_rn(v); }
    for (int i=i0; i<D*D; i+=st){ int n=i/D, k=i%D; gWp_h[i] = __float2half_rn(Wp[k*D+n]); }
}

// 128x128-tile split-fp16 GEMM (2 products: Ah*B + Al*B), double-buffered, ldmatrix.
#define SSTR 56
#define SLAB (128*SSTR)
#define GEMM_SMEM (6*SLAB*2)

template<int EPI>
__global__ __launch_bounds__(256,2)
void gemm128(int KT, const float* __restrict__ A,
             const float* __restrict__ bias0, const float* __restrict__ bias1,
             float* __restrict__ outF)
{
    extern __shared__ __half smh[];
    __half* sAh = smh;
    __half* sAl = smh + 2*SLAB;
    __half* sBh = smh + 4*SLAB;

    const int tid = threadIdx.x, lane = tid&31, warp = tid>>5;
    const int wm = warp>>1, wn = warp&1;
    const int m0 = blockIdx.y*128, n0 = blockIdx.x*128;
    const __half* Bh = (EPI==0)?gWq_h:(EPI==1)?gWkv_h:gWp_h;
    const float*  Ap = (EPI==2)?gO:A;

    const int arA[4] = { (tid+0)>>3, (tid+256)>>3, (tid+512)>>3, (tid+768)>>3 };
    const int acA    = (tid&7)<<2;
    const int brB[2] = { (tid+0)>>2, (tid+256)>>2 };
    const int bcB    = (tid&3)<<3;

    const unsigned smbase = (unsigned)__cvta_generic_to_shared(smh);
    const int aoff = (wm*32 + (lane&15))*SSTR + ((lane&16)?8:0);
    const int boff = (wn*64 + (lane&7) + ((lane&16)?8:0))*SSTR + ((lane&8)?8:0);

    float acc[2][8][4] = {};
    float4 pa[4]; uint4 pb[2];

    const int NS = KT >> 5;

    #pragma unroll
    for (int i=0;i<4;i++) pa[i] = *(const float4*)(Ap + (size_t)(m0+arA[i])*KT + acA);
    #pragma unroll
    for (int i=0;i<2;i++) pb[i] = *(const uint4*)(Bh + (size_t)(n0+brB[i])*KT + bcB);
    #pragma unroll
    for (int i=0;i<4;i++){
        int o = arA[i]*SSTR + acA;
        fsplit(pa[i].x, sAh[o],   sAl[o]);
        fsplit(pa[i].y, sAh[o+1], sAl[o+1]);
        fsplit(pa[i].z, sAh[o+2], sAl[o+2]);
        fsplit(pa[i].w, sAh[o+3], sAl[o+3]);
    }
    #pragma unroll
    for (int i=0;i<2;i++) *(uint4*)&sBh[brB[i]*SSTR + bcB] = pb[i];
    __syncthreads();

    for (int s=0; s<NS; s++){
        const int buf = s&1;
        const bool more = (s+1 < NS);
        if (more){
            const int kk = (s+1)<<5;
            #pragma unroll
            for (int i=0;i<4;i++) pa[i] = *(const float4*)(Ap + (size_t)(m0+arA[i])*KT + kk + acA);
            #pragma unroll
            for (int i=0;i<2;i++) pb[i] = *(const uint4*)(Bh + (size_t)(n0+brB[i])*KT + kk + bcB);
        }
        const unsigned aH = smbase + (unsigned)(buf*SLAB + aoff)*2u;
        const unsigned aL = smbase + (unsigned)(2*SLAB + buf*SLAB + aoff)*2u;
        const unsigned bB = smbase + (unsigned)(4*SLAB + buf*SLAB + boff)*2u;
        #pragma unroll
        for (int ks=0; ks<2; ks++){
            unsigned ah[2][4], al[2][4];
            #pragma unroll
            for (int mt=0;mt<2;mt++){
                ldsm4(aH + (unsigned)(mt*16*SSTR + ks*16)*2u, ah[mt]);
                ldsm4(aL + (unsigned)(mt*16*SSTR + ks*16)*2u, al[mt]);
            }
            #pragma unroll
            for (int nt2=0; nt2<4; nt2++){
                unsigned bb[4];
                ldsm4(bB + (unsigned)(nt2*16*SSTR + ks*16)*2u, bb);
                #pragma unroll
                for (int mt=0;mt<2;mt++){
                    mma16816(acc[mt][2*nt2],   ah[mt], bb[0], bb[1]);
                    mma16816(acc[mt][2*nt2],   al[mt], bb[0], bb[1]);
                    mma16816(acc[mt][2*nt2+1], ah[mt], bb[2], bb[3]);
                    mma16816(acc[mt][2*nt2+1], al[mt], bb[2], bb[3]);
                }
            }
        }
        if (more){
            const int nb = buf^1;
            #pragma unroll
            for (int i=0;i<4;i++){
                int o = nb*SLAB + arA[i]*SSTR + acA;
                fsplit(pa[i].x, sAh[o],   sAl[o]);
                fsplit(pa[i].y, sAh[o+1], sAl[o+1]);
                fsplit(pa[i].z, sAh[o+2], sAl[o+2]);
                fsplit(pa[i].w, sAh[o+3], sAl[o+3]);
            }
            #pragma unroll
            for (int i=0;i<2;i++) *(uint4*)&sBh[nb*SLAB + brB[i]*SSTR + bcB] = pb[i];
        }
        __syncthreads();
    }

    #pragma unroll
    for (int mt=0;mt<2;mt++){
        #pragma unroll
        for (int nt=0;nt<8;nt++){
            int r = m0 + wm*32 + mt*16 + (lane>>2);
            int c = n0 + wn*64 + nt*8 + (lane&3)*2;
            float v00=acc[mt][nt][0], v01=acc[mt][nt][1];
            float v10=acc[mt][nt][2], v11=acc[mt][nt][3];
            if (EPI == 0){
                float b0=bias0[c], b1=bias0[c+1];
                *(__half2*)&gQh[(size_t)r*D+c]     = __floats2half2_rn(v00+b0, v01+b1);
                *(__half2*)&gQh[(size_t)(r+8)*D+c] = __floats2half2_rn(v10+b0, v11+b1);
            } else if (EPI == 1){
                bool isV = (c >= D);
                __half* dst = isV ? gV : gK;
                const float* bb = isV ? bias1 : bias0;
                int cc = c & (D-1);
                float b0=bb[cc], b1=bb[cc+1];
                *(__half2*)&dst[(size_t)r*D+cc]     = __floats2half2_rn(v00+b0, v01+b1);
                *(__half2*)&dst[(size_t)(r+8)*D+cc] = __floats2half2_rn(v10+b0, v11+b1);
            } else {
                float b0=bias0[c], b1=bias0[c+1];
                outF[(size_t)r*D+c]       = v00+b0;
                outF[(size_t)r*D+c+1]     = v01+b1;
                outF[(size_t)(r+8)*D+c]   = v10+b0;
                outF[(size_t)(r+8)*D+c+1] = v11+b1;
            }
        }
    }
}

// One CTA per window. All tile loads via cp.async (deep MLP).
// smem layout (bytes):
//   sQ   [0,      33792)  Q fp16 64x264   (reused as Ph 64x168 after S)
//   sPl  [33792,  55296)  P-lo 64x168
//   sKV  [55296, 139776)  K then V, 160x264 (rows 147..159 zero)
//   sS   [139776,180736)  S fp32 64x160
//   sM   [180736,190340)  mask 49x49 fp32
#define OFF_PL 33792u
#define OFF_KV 55296u
#define OFF_S  139776u
#define OFF_M  180736u
#define SMEM_BYTES 190464
__global__ __launch_bounds__(256)
void attn_kernel(const float* __restrict__ mask)
{
    extern __shared__ char sm[];
    __half* sQ  = (__half*)sm;
    __half* sPl = (__half*)(sm + OFF_PL);
    __half* sKV = (__half*)(sm + OFF_KV);
    float*  sS  = (float*)(sm + OFF_S);
    float*  sM  = (float*)(sm + OFF_M);
    __half* sPh = sQ;

    const int tid = threadIdx.x, lane = tid&31, warp = tid>>5;
    const int t = blockIdx.x;
    const size_t qb = (size_t)t*WA*D, kvb = (size_t)t*3*WA*D;
    const unsigned smb = (unsigned)__cvta_generic_to_shared(sm);

    // ---- async loads: group A = Q+K, group B = mask ----
    for (int i=tid; i<49*32; i+=256){ int r=i>>5, g=(i&31)<<3;
        cpa16(smb + (unsigned)(r*264+g)*2u, gQh + qb + (size_t)r*D + g); }
    for (int i=tid; i<147*32; i+=256){ int r=i>>5, g=(i&31)<<3;
        cpa16(smb + OFF_KV + (unsigned)(r*264+g)*2u, gK + kvb + (size_t)r*D + g); }
    CP_COMMIT();
    for (int i=tid; i<WA*WA; i+=256)
        cpa4(smb + OFF_M + (unsigned)i*4u, mask + (size_t)(t&63)*WA*WA + i);
    CP_COMMIT();
    // zero KV pad rows 147..159 (plain STS, disjoint from cp.async targets)
    for (int i=tid; i<13*33; i+=256){ int r=147 + i/33, c=(i%33)*8;
        *(uint4*)&sKV[r*264+c] = make_uint4(0,0,0,0); }
    CP_WAIT1();            // group A (Q+K) complete
    __syncthreads();

    // ---- S = Q @ K^T (single-product Q fp16) ----
    {
        const int wmS = warp>>1, wnS = warp&1;
        const unsigned aQ = smb + (unsigned)((wmS*16 + (lane&15))*264 + ((lane&16)?8:0))*2u;
        const unsigned bK = smb + OFF_KV
            + (unsigned)((wnS*80 + (lane&7) + ((lane&16)?8:0))*264 + ((lane&8)?8:0))*2u;
        float acc[10][4] = {};
        #pragma unroll
        for (int ks=0; ks<16; ks++){
            unsigned ah[4];
            ldsm4(aQ + ks*32u, ah);
            #pragma unroll
            for (int nt2=0; nt2<5; nt2++){
                unsigned bb[4];
                ldsm4(bK + (unsigned)(nt2*16*264)*2u + ks*32u, bb);
                mma16816(acc[2*nt2],   ah, bb[0], bb[1]);
                mma16816(acc[2*nt2+1], ah, bb[2], bb[3]);
            }
        }
        #pragma unroll
        for (int j=0;j<10;j++){
            int r = wmS*16 + (lane>>2), c = (wnS*10+j)*8 + (lane&3)*2;
            sS[r*160+c]=acc[j][0]; sS[r*160+c+1]=acc[j][1];
            sS[(r+8)*160+c]=acc[j][2]; sS[(r+8)*160+c+1]=acc[j][3];
        }
    }
    CP_WAIT0();            // group B (mask) complete
    __syncthreads();

    // ---- V via cp.async into sKV (group C); latency hides under softmax ----
    for (int i=tid; i<147*32; i+=256){ int r=i>>5, g=(i&31)<<3;
        cpa16(smb + OFF_KV + (unsigned)(r*264+g)*2u, gV + kvb + (size_t)r*D + g); }
    CP_COMMIT();

    // ---- softmax rows (fp32) -> split P ----
    for (int r=warp; r<49; r+=8){
        float vals[5]; float mx = -1e30f;
        #pragma unroll
        for (int i=0;i<5;i++){ int c = lane + 32*i; float v = -1e30f;
            if (c < 147){ int cm = (c>=98)?c-98:(c>=49)?c-49:c;
                v = sS[r*160+c]*SCALE_F + sM[r*49+cm]; }
            vals[i]=v; mx=fmaxf(mx,v); }
        #pragma unroll
        for (int o=16;o;o>>=1) mx = fmaxf(mx, __shfl_xor_sync(0xffffffffu, mx, o));
        float s = 0.f;
        #pragma unroll
        for (int i=0;i<5;i++){ int c = lane + 32*i;
            float e = (c<147) ? __expf(vals[i]-mx) : 0.f; vals[i]=e; s+=e; }
        #pragma unroll
        for (int o=16;o;o>>=1) s += __shfl_xor_sync(0xffffffffu, s, o);
        float inv = 1.f/s;
        #pragma unroll
        for (int i=0;i<5;i++){ int c = lane + 32*i; float p = vals[i]*inv;
            __half h,l; fsplit(p,h,l); sPh[r*168+c]=h; sPl[r*168+c]=l; }
    }
    for (int i=tid; i<15*21; i+=256){ int r=49 + i/21, c=(i%21)*8;
        *(uint4*)&sPh[r*168+c] = make_uint4(0,0,0,0);
        *(uint4*)&sPl[r*168+c] = make_uint4(0,0,0,0); }
    CP_WAIT0();            // group C (V) complete
    __syncthreads();

    // ---- O = P @ V : M=64 (q), N=256 (d), K=160 (toks); split-P, trans-B ldmatrix ----
    {
        const int wmP = warp&1, wnP = warp>>1;
        const unsigned aPh = smb + (unsigned)((wmP*32 + (lane&15))*168 + ((lane&16)?8:0))*2u;
        const unsigned aPl = aPh + OFF_PL;
        const unsigned bV  = smb + OFF_KV
            + (unsigned)((lane&15)*264 + wnP*64 + ((lane&16)?8:0))*2u;
        float acc[2][8][4] = {};
        #pragma unroll
        for (int ks=0; ks<10; ks++){
            unsigned ph[2][4], pl[2][4];
            #pragma unroll
            for (int mt=0;mt<2;mt++){
                ldsm4(aPh + (unsigned)(mt*16*168 + ks*16)*2u, ph[mt]);
                ldsm4(aPl + (unsigned)(mt*16*168 + ks*16)*2u, pl[mt]);
            }
            #pragma unroll
            for (int nt2=0; nt2<4; nt2++){
                unsigned vb[4];
                ldsm4t(bV + (unsigned)(ks*16*264 + nt2*16)*2u, vb);
                #pragma unroll
                for (int mt=0;mt<2;mt++){
                    mma16816(acc[mt][2*nt2],   ph[mt], vb[0], vb[1]);
                    mma16816(acc[mt][2*nt2],   pl[mt], vb[0], vb[1]);
                    mma16816(acc[mt][2*nt2+1], ph[mt], vb[2], vb[3]);
                    mma16816(acc[mt][2*nt2+1], pl[mt], vb[2], vb[3]);
                }
            }
        }
        float* Ow = gO + (size_t)t*WA*D;
        #pragma unroll
        for (int mt=0;mt<2;mt++){
            #pragma unroll
            for (int nt=0;nt<8;nt++){
                int q  = wmP*32 + mt*16 + (lane>>2);
                int d0 = wnP*64 + nt*8 + (lane&3)*2;
                if (q < 49){
                    Ow[d0*49+q]     = acc[mt][nt][0];
                    Ow[(d0+1)*49+q] = acc[mt][nt][1];
                }
                if (q+8 < 49){
                    Ow[d0*49+q+8]     = acc[mt][nt][2];
                    Ow[(d0+1)*49+q+8] = acc[mt][nt][3];
                }
            }
        }
    }
}

extern "C" void kernel_launch(void* const* d_in, const int* in_sizes, int n_in,
                              void* d_out, int out_size)
{
    const float* x    = (const float*)d_in[0];
    const float* mask = (const float*)d_in[1];
    const float* Wq = (const float*)d_in[2]; const float* bq = (const float*)d_in[3];
    const float* Wk = (const float*)d_in[4]; const float* bk = (const float*)d_in[5];
    const float* Wv = (const float*)d_in[6]; const float* bv = (const float*)d_in[7];
    const float* Wp = (const float*)d_in[8]; const float* bp = (const float*)d_in[9];
    float* out = (float*)d_out;

    cudaFuncSetAttribute(attn_kernel, cudaFuncAttributeMaxDynamicSharedMemorySize, SMEM_BYTES);
    cudaFuncSetAttribute(gemm128<0>, cudaFuncAttributeMaxDynamicSharedMemorySize, GEMM_SMEM);
    cudaFuncSetAttribute(gemm128<1>, cudaFuncAttributeMaxDynamicSharedMemorySize, GEMM_SMEM);
    cudaFuncSetAttribute(gemm128<2>, cudaFuncAttributeMaxDynamicSharedMemorySize, GEMM_SMEM);

    prep_weights<<<256,256>>>(Wq, Wk, Wv, Wp);
    gemm128<0><<<dim3(2,784), 256, GEMM_SMEM>>>(CIN, x + (size_t)3*TW*WA*CIN, bq, nullptr, nullptr);
    gemm128<1><<<dim3(4,2352), 256, GEMM_SMEM>>>(CIN, x, bk, bv, nullptr);
    attn_kernel<<<TW, 256, SMEM_BYTES>>>(mask);
    gemm128<2><<<dim3(2,784), 256, GEMM_SMEM>>>(D, nullptr, bp, nullptr, out);
}

// round 12
// speedup vs baseline: 1.8440x; 1.3913x over previous
#include <cuda_runtime.h>
#include <cuda_fp16.h>

#define TW 2048
#define WA 49
#define NQ (TW*WA)
#define NKV (3*TW*WA)
#define CIN 512
#define D 256
#define SCALE_F 0.17677669529663687f

__device__ __half gWq_h[D*CIN];
__device__ __half gWkv_h[2*D*CIN];
__device__ __half gWp_h[D*D];
__device__ __half gQh[(size_t)NQ*D];
__device__ __half gK[(size_t)NKV*D], gV[(size_t)NKV*D];
__device__ float  gO[(size_t)NQ*D];

__device__ __forceinline__ void fsplit(float v, __half& hi, __half& lo){
    hi = __float2half_rn(v);
    lo = __float2half_rn(v - __half2float(hi));
}

__device__ __forceinline__ void mma16816(float c[4], const unsigned a[4], unsigned b0, unsigned b1){
    asm volatile(
      "mma.sync.aligned.m16n8k16.row.col.f32.f16.f16.f32 "
      "{%0,%1,%2,%3},{%4,%5,%6,%7},{%8,%9},{%0,%1,%2,%3};\n"
      : "+f"(c[0]), "+f"(c[1]), "+f"(c[2]), "+f"(c[3])
      : "r"(a[0]), "r"(a[1]), "r"(a[2]), "r"(a[3]), "r"(b0), "r"(b1));
}

__device__ __forceinline__ void ldsm4(unsigned addr, unsigned r[4]){
    asm volatile("ldmatrix.sync.aligned.m8n8.x4.shared.b16 {%0,%1,%2,%3}, [%4];\n"
      : "=r"(r[0]), "=r"(r[1]), "=r"(r[2]), "=r"(r[3]) : "r"(addr));
}

__device__ __forceinline__ void ldsm4t(unsigned addr, unsigned r[4]){
    asm volatile("ldmatrix.sync.aligned.m8n8.x4.trans.shared.b16 {%0,%1,%2,%3}, [%4];\n"
      : "=r"(r[0]), "=r"(r[1]), "=r"(r[2]), "=r"(r[3]) : "r"(addr));
}

__device__ __forceinline__ void cpa16(unsigned dst, const void* src){
    asm volatile("cp.async.cg.shared.global [%0], [%1], 16;\n" :: "r"(dst), "l"(src) : "memory");
}
__device__ __forceinline__ void cpa4(unsigned dst, const void* src){
    asm volatile("cp.async.ca.shared.global [%0], [%1], 4;\n" :: "r"(dst), "l"(src) : "memory");
}
#define CP_COMMIT()  asm volatile("cp.async.commit_group;\n" ::: "memory")
#define CP_WAIT0()   asm volatile("cp.async.wait_group 0;\n" ::: "memory")
#define CP_WAIT1()   asm volatile("cp.async.wait_group 1;\n" ::: "memory")

__global__ void prep_weights(const float* __restrict__ Wq, const float* __restrict__ Wk,
                             const float* __restrict__ Wv, const float* __restrict__ Wp){
    int i0 = blockIdx.x*blockDim.x + threadIdx.x, st = gridDim.x*blockDim.x;
    for (int i=i0; i<D*CIN; i+=st){ int n=i/CIN, k=i%CIN; gWq_h[i] = __float2half_rn(Wq[k*D+n]); }
    for (int i=i0; i<2*D*CIN; i+=st){ int n=i/CIN, k=i%CIN;
        float v = (n<D) ? Wk[k*D+n] : Wv[k*D+n-D]; gWkv_h[i] = __float2half_rn(v); }
    for (int i=i0; i<D*D; i+=st){ int n=i/D, k=i%D; gWp_h[i] = __float2half_rn(Wp[k*D+n]); }
}

// ---------------- 128x256-tile GEMM, NPROD mma products, cp.async B, dbl-buffered ----------------
// smem (halves): sAh buf*5120 | sB 10240 + buf*10240 | sAl 30720 + buf*5120 (NPROD==2)
#define ASTR 40
template<int EPI, int NPROD>
__global__ __launch_bounds__(256,1)
void gemm256(int KT, const float* __restrict__ A,
             const float* __restrict__ bias0, const float* __restrict__ bias1,
             float* __restrict__ outF)
{
    extern __shared__ __half smh[];
    const int tid = threadIdx.x, lane = tid&31, warp = tid>>5;
    const int wm = warp>>2, wn = warp&3;
    const int m0 = blockIdx.y*128, n0 = blockIdx.x*256;
    const __half* Bg = (EPI==0)?gWq_h:(EPI==1)?gWkv_h:gWp_h;
    const float*  Ap = (EPI==2)?gO:A;

    const int arA[4] = {(tid)>>3,(tid+256)>>3,(tid+512)>>3,(tid+768)>>3};
    const int acA    = (tid&7)<<2;
    const int brB[4] = {(tid)>>2,(tid+256)>>2,(tid+512)>>2,(tid+768)>>2};
    const int bcB    = (tid&3)<<3;

    const unsigned smb = (unsigned)__cvta_generic_to_shared(smh);
    const int aoff = (wm*64 + (lane&15))*ASTR + ((lane&16)?8:0);
    const int boff = (wn*64 + (lane&7) + ((lane&16)?8:0))*ASTR + ((lane&8)?8:0);

    float acc[4][8][4] = {};
    float4 pa[4];

    const int NS = KT >> 5;

    // prologue: B slab 0 via cp.async, A slab 0 via LDG+fsplit+STS
    #pragma unroll
    for (int i=0;i<4;i++)
        cpa16(smb + (10240u + (unsigned)(brB[i]*ASTR + bcB))*2u,
              Bg + (size_t)(n0+brB[i])*KT + bcB);
    CP_COMMIT();
    #pragma unroll
    for (int i=0;i<4;i++) pa[i] = *(const float4*)(Ap + (size_t)(m0+arA[i])*KT + acA);
    #pragma unroll
    for (int i=0;i<4;i++){
        int o = arA[i]*ASTR + acA;
        __half h0,h1,h2,h3,l0,l1,l2,l3;
        fsplit(pa[i].x,h0,l0); fsplit(pa[i].y,h1,l1);
        fsplit(pa[i].z,h2,l2); fsplit(pa[i].w,h3,l3);
        *(__half2*)&smh[o]   = __halves2half2(h0,h1);
        *(__half2*)&smh[o+2] = __halves2half2(h2,h3);
        if (NPROD==2){
            *(__half2*)&smh[30720+o]   = __halves2half2(l0,l1);
            *(__half2*)&smh[30720+o+2] = __halves2half2(l2,l3);
        }
    }

    for (int s=0; s<NS; s++){
        const int buf = s&1, nb = buf^1;
        const bool more = (s+1 < NS);
        if (more){
            const int kk = (s+1)<<5;
            #pragma unroll
            for (int i=0;i<4;i++)
                cpa16(smb + (10240u + (unsigned)(nb*10240 + brB[i]*ASTR + bcB))*2u,
                      Bg + (size_t)(n0+brB[i])*KT + kk + bcB);
            CP_COMMIT();
            #pragma unroll
            for (int i=0;i<4;i++) pa[i] = *(const float4*)(Ap + (size_t)(m0+arA[i])*KT + kk + acA);
            CP_WAIT1();
        } else {
            CP_WAIT0();
        }
        __syncthreads();

        const unsigned aH = smb + (unsigned)(buf*5120 + aoff)*2u;
        const unsigned aL = smb + (unsigned)(30720 + buf*5120 + aoff)*2u;
        const unsigned bB = smb + (unsigned)(10240 + buf*10240 + boff)*2u;
        #pragma unroll
        for (int ks=0; ks<2; ks++){
            unsigned ah[4][4], al[4][4];
            #pragma unroll
            for (int mt=0;mt<4;mt++){
                ldsm4(aH + (unsigned)(mt*16*ASTR + ks*16)*2u, ah[mt]);
                if (NPROD==2) ldsm4(aL + (unsigned)(mt*16*ASTR + ks*16)*2u, al[mt]);
            }
            #pragma unroll
            for (int nt2=0; nt2<4; nt2++){
                unsigned bb[4];
                ldsm4(bB + (unsigned)(nt2*16*ASTR + ks*16)*2u, bb);
                #pragma unroll
                for (int mt=0;mt<4;mt++){
                    mma16816(acc[mt][2*nt2],   ah[mt], bb[0], bb[1]);
                    mma16816(acc[mt][2*nt2+1], ah[mt], bb[2], bb[3]);
                    if (NPROD==2){
                        mma16816(acc[mt][2*nt2],   al[mt], bb[0], bb[1]);
                        mma16816(acc[mt][2*nt2+1], al[mt], bb[2], bb[3]);
                    }
                }
            }
        }
        if (more){
            #pragma unroll
            for (int i=0;i<4;i++){
                int o = nb*5120 + arA[i]*ASTR + acA;
                __half h0,h1,h2,h3,l0,l1,l2,l3;
                fsplit(pa[i].x,h0,l0); fsplit(pa[i].y,h1,l1);
                fsplit(pa[i].z,h2,l2); fsplit(pa[i].w,h3,l3);
                *(__half2*)&smh[o]   = __halves2half2(h0,h1);
                *(__half2*)&smh[o+2] = __halves2half2(h2,h3);
                if (NPROD==2){
                    *(__half2*)&smh[30720+o]   = __halves2half2(l0,l1);
                    *(__half2*)&smh[30720+o+2] = __halves2half2(l2,l3);
                }
            }
        }
        __syncthreads();
    }

    #pragma unroll
    for (int mt=0;mt<4;mt++){
        #pragma unroll
        for (int nt=0;nt<8;nt++){
            int r = m0 + wm*64 + mt*16 + (lane>>2);
            int c = n0 + wn*64 + nt*8 + (lane&3)*2;
            float v00=acc[mt][nt][0], v01=acc[mt][nt][1];
            float v10=acc[mt][nt][2], v11=acc[mt][nt][3];
            if (EPI == 0){
                float b0=bias0[c], b1=bias0[c+1];
                *(__half2*)&gQh[(size_t)r*D+c]     = __floats2half2_rn(v00+b0, v01+b1);
                *(__half2*)&gQh[(size_t)(r+8)*D+c] = __floats2half2_rn(v10+b0, v11+b1);
            } else if (EPI == 1){
                bool isV = (c >= D);
                __half* dst = isV ? gV : gK;
                const float* bb = isV ? bias1 : bias0;
                int cc = c & (D-1);
                float b0=bb[cc], b1=bb[cc+1];
                *(__half2*)&dst[(size_t)r*D+cc]     = __floats2half2_rn(v00+b0, v01+b1);
                *(__half2*)&dst[(size_t)(r+8)*D+cc] = __floats2half2_rn(v10+b0, v11+b1);
            } else {
                float b0=bias0[c], b1=bias0[c+1];
                outF[(size_t)r*D+c]       = v00+b0;
                outF[(size_t)r*D+c+1]     = v01+b1;
                outF[(size_t)(r+8)*D+c]   = v10+b0;
                outF[(size_t)(r+8)*D+c+1] = v11+b1;
            }
        }
    }
}
#define GEMM_SMEM_1 61440
#define GEMM_SMEM_2 81920

// ---------------- attention (unchanged from R11) ----------------
#define OFF_PL 33792u
#define OFF_KV 55296u
#define OFF_S  139776u
#define OFF_M  180736u
#define SMEM_BYTES 190464
__global__ __launch_bounds__(256)
void attn_kernel(const float* __restrict__ mask)
{
    extern __shared__ char sm[];
    __half* sQ  = (__half*)sm;
    __half* sPl = (__half*)(sm + OFF_PL);
    __half* sKV = (__half*)(sm + OFF_KV);
    float*  sS  = (float*)(sm + OFF_S);
    float*  sM  = (float*)(sm + OFF_M);
    __half* sPh = sQ;

    const int tid = threadIdx.x, lane = tid&31, warp = tid>>5;
    const int t = blockIdx.x;
    const size_t qb = (size_t)t*WA*D, kvb = (size_t)t*3*WA*D;
    const unsigned smb = (unsigned)__cvta_generic_to_shared(sm);

    for (int i=tid; i<49*32; i+=256){ int r=i>>5, g=(i&31)<<3;
        cpa16(smb + (unsigned)(r*264+g)*2u, gQh + qb + (size_t)r*D + g); }
    for (int i=tid; i<147*32; i+=256){ int r=i>>5, g=(i&31)<<3;
        cpa16(smb + OFF_KV + (unsigned)(r*264+g)*2u, gK + kvb + (size_t)r*D + g); }
    CP_COMMIT();
    for (int i=tid; i<WA*WA; i+=256)
        cpa4(smb + OFF_M + (unsigned)i*4u, mask + (size_t)(t&63)*WA*WA + i);
    CP_COMMIT();
    for (int i=tid; i<13*33; i+=256){ int r=147 + i/33, c=(i%33)*8;
        *(uint4*)&sKV[r*264+c] = make_uint4(0,0,0,0); }
    CP_WAIT1();
    __syncthreads();

    {
        const int wmS = warp>>1, wnS = warp&1;
        const unsigned aQ = smb + (unsigned)((wmS*16 + (lane&15))*264 + ((lane&16)?8:0))*2u;
        const unsigned bK = smb + OFF_KV
            + (unsigned)((wnS*80 + (lane&7) + ((lane&16)?8:0))*264 + ((lane&8)?8:0))*2u;
        float acc[10][4] = {};
        #pragma unroll
        for (int ks=0; ks<16; ks++){
            unsigned ah[4];
            ldsm4(aQ + ks*32u, ah);
            #pragma unroll
            for (int nt2=0; nt2<5; nt2++){
                unsigned bb[4];
                ldsm4(bK + (unsigned)(nt2*16*264)*2u + ks*32u, bb);
                mma16816(acc[2*nt2],   ah, bb[0], bb[1]);
                mma16816(acc[2*nt2+1], ah, bb[2], bb[3]);
            }
        }
        #pragma unroll
        for (int j=0;j<10;j++){
            int r = wmS*16 + (lane>>2), c = (wnS*10+j)*8 + (lane&3)*2;
            sS[r*160+c]=acc[j][0]; sS[r*160+c+1]=acc[j][1];
            sS[(r+8)*160+c]=acc[j][2]; sS[(r+8)*160+c+1]=acc[j][3];
        }
    }
    CP_WAIT0();
    __syncthreads();

    for (int i=tid; i<147*32; i+=256){ int r=i>>5, g=(i&31)<<3;
        cpa16(smb + OFF_KV + (unsigned)(r*264+g)*2u, gV + kvb + (size_t)r*D + g); }
    CP_COMMIT();

    for (int r=warp; r<49; r+=8){
        float vals[5]; float mx = -1e30f;
        #pragma unroll
        for (int i=0;i<5;i++){ int c = lane + 32*i; float v = -1e30f;
            if (c < 147){ int cm = (c>=98)?c-98:(c>=49)?c-49:c;
                v = sS[r*160+c]*SCALE_F + sM[r*49+cm]; }
            vals[i]=v; mx=fmaxf(mx,v); }
        #pragma unroll
        for (int o=16;o;o>>=1) mx = fmaxf(mx, __shfl_xor_sync(0xffffffffu, mx, o));
        float s = 0.f;
        #pragma unroll
        for (int i=0;i<5;i++){ int c = lane + 32*i;
            float e = (c<147) ? __expf(vals[i]-mx) : 0.f; vals[i]=e; s+=e; }
        #pragma unroll
        for (int o=16;o;o>>=1) s += __shfl_xor_sync(0xffffffffu, s, o);
        float inv = 1.f/s;
        #pragma unroll
        for (int i=0;i<5;i++){ int c = lane + 32*i; float p = vals[i]*inv;
            __half h,l; fsplit(p,h,l); sPh[r*168+c]=h; sPl[r*168+c]=l; }
    }
    for (int i=tid; i<15*21; i+=256){ int r=49 + i/21, c=(i%21)*8;
        *(uint4*)&sPh[r*168+c] = make_uint4(0,0,0,0);
        *(uint4*)&sPl[r*168+c] = make_uint4(0,0,0,0); }
    CP_WAIT0();
    __syncthreads();

    {
        const int wmP = warp&1, wnP = warp>>1;
        const unsigned aPh = smb + (unsigned)((wmP*32 + (lane&15))*168 + ((lane&16)?8:0))*2u;
        const unsigned aPl = aPh + OFF_PL;
        const unsigned bV  = smb + OFF_KV
            + (unsigned)((lane&15)*264 + wnP*64 + ((lane&16)?8:0))*2u;
        float acc[2][8][4] = {};
        #pragma unroll
        for (int ks=0; ks<10; ks++){
            unsigned ph[2][4], pl[2][4];
            #pragma unroll
            for (int mt=0;mt<2;mt++){
                ldsm4(aPh + (unsigned)(mt*16*168 + ks*16)*2u, ph[mt]);
                ldsm4(aPl + (unsigned)(mt*16*168 + ks*16)*2u, pl[mt]);
            }
            #pragma unroll
            for (int nt2=0; nt2<4; nt2++){
                unsigned vb[4];
                ldsm4t(bV + (unsigned)(ks*16*264 + nt2*16)*2u, vb);
                #pragma unroll
                for (int mt=0;mt<2;mt++){
                    mma16816(acc[mt][2*nt2],   ph[mt], vb[0], vb[1]);
                    mma16816(acc[mt][2*nt2],   pl[mt], vb[0], vb[1]);
                    mma16816(acc[mt][2*nt2+1], ph[mt], vb[2], vb[3]);
                    mma16816(acc[mt][2*nt2+1], pl[mt], vb[2], vb[3]);
                }
            }
        }
        float* Ow = gO + (size_t)t*WA*D;
        #pragma unroll
        for (int mt=0;mt<2;mt++){
            #pragma unroll
            for (int nt=0;nt<8;nt++){
                int q  = wmP*32 + mt*16 + (lane>>2);
                int d0 = wnP*64 + nt*8 + (lane&3)*2;
                if (q < 49){
                    Ow[d0*49+q]     = acc[mt][nt][0];
                    Ow[(d0+1)*49+q] = acc[mt][nt][1];
                }
                if (q+8 < 49){
                    Ow[d0*49+q+8]     = acc[mt][nt][2];
                    Ow[(d0+1)*49+q+8] = acc[mt][nt][3];
                }
            }
        }
    }
}

extern "C" void kernel_launch(void* const* d_in, const int* in_sizes, int n_in,
                              void* d_out, int out_size)
{
    const float* x    = (const float*)d_in[0];
    const float* mask = (const float*)d_in[1];
    const float* Wq = (const float*)d_in[2]; const float* bq = (const float*)d_in[3];
    const float* Wk = (const float*)d_in[4]; const float* bk = (const float*)d_in[5];
    const float* Wv = (const float*)d_in[6]; const float* bv = (const float*)d_in[7];
    const float* Wp = (const float*)d_in[8]; const float* bp = (const float*)d_in[9];
    float* out = (float*)d_out;

    cudaFuncSetAttribute(attn_kernel, cudaFuncAttributeMaxDynamicSharedMemorySize, SMEM_BYTES);
    cudaFuncSetAttribute((gemm256<0,1>), cudaFuncAttributeMaxDynamicSharedMemorySize, GEMM_SMEM_1);
    cudaFuncSetAttribute((gemm256<1,1>), cudaFuncAttributeMaxDynamicSharedMemorySize, GEMM_SMEM_1);
    cudaFuncSetAttribute((gemm256<2,2>), cudaFuncAttributeMaxDynamicSharedMemorySize, GEMM_SMEM_2);

    prep_weights<<<256,256>>>(Wq, Wk, Wv, Wp);
    gemm256<0,1><<<dim3(1,784), 256, GEMM_SMEM_1>>>(CIN, x + (size_t)3*TW*WA*CIN, bq, nullptr, nullptr);
    gemm256<1,1><<<dim3(2,2352), 256, GEMM_SMEM_1>>>(CIN, x, bk, bv, nullptr);
    attn_kernel<<<TW, 256, SMEM_BYTES>>>(mask);
    gemm256<2,2><<<dim3(1,784), 256, GEMM_SMEM_2>>>(D, nullptr, bp, nullptr, out);
}